// round 9
// baseline (speedup 1.0000x reference)
#include <cuda_runtime.h>
#include <cstdint>

#define CIN  10
#define C    64
#define SMAX 30001
#define EPS  1e-3f
#define FULLMASK 0xffffffffu

typedef unsigned long long u64;

// ---------------- parameter staging (read by k_pipe into shared) ----------------
struct Params {
    u64   Wfp[32 * CIN];   // BN-folded linear weights, channel-pair packed
    u64   biasp[32];
    u64   dwp[32];
    float xg[C];
};
__device__ Params g_stage;

// ---------------- device scratch ----------------
__device__ float g_m1[CIN];
__device__ float g_m2[55];
__device__ float g_Wf[C * CIN];
__device__ float g_bias[C];
__device__ float g_gsum[C];
__device__ int   g_segstart[SMAX];
// per-pillar partials, 2 slots (pillar-start subtile / spill subtile)
__device__ float g_pmax[(size_t)2 * SMAX * C];
__device__ float g_psum[(size_t)2 * SMAX * C];

// ---------------- packed f32x2 helpers ----------------
__device__ __forceinline__ u64 pack2(float lo, float hi) {
    u64 r; asm("mov.b64 %0, {%1, %2};" : "=l"(r) : "f"(lo), "f"(hi)); return r;
}
__device__ __forceinline__ void unpack2(u64 v, float& lo, float& hi) {
    asm("mov.b64 {%0, %1}, %2;" : "=f"(lo), "=f"(hi) : "l"(v));
}
__device__ __forceinline__ u64 fma2(u64 a, u64 b, u64 c) {
    u64 d; asm("fma.rn.f32x2 %0, %1, %2, %3;" : "=l"(d) : "l"(a), "l"(b), "l"(c)); return d;
}
__device__ __forceinline__ u64 mul2(u64 a, u64 b) {
    u64 d; asm("mul.rn.f32x2 %0, %1, %2;" : "=l"(d) : "l"(a), "l"(b)); return d;
}

__device__ __forceinline__ float sigmoidf_fast(float z) {
    return __fdividef(1.0f, 1.0f + __expf(-z));
}
__device__ __forceinline__ float warp_sum(float v) {
#pragma unroll
    for (int o = 16; o > 0; o >>= 1) v += __shfl_down_sync(FULLMASK, v, o);
    return v;
}

// ---------------- K1: zero accumulators + segment boundaries ----------------
__global__ void k_bounds(const int* __restrict__ unq, int n, int s_count) {
    if (blockIdx.x == 0) {
        int t = threadIdx.x;
        if (t < CIN) g_m1[t] = 0.0f;
        if (t < 55)  g_m2[t] = 0.0f;
        if (t < C)   g_gsum[t] = 0.0f;
    }
    int i = blockIdx.x * blockDim.x + threadIdx.x;
    if (i >= n) return;
    int cur = unq[i];
    if (i == 0) {
        for (int t = 0; t <= cur; t++) g_segstart[t] = 0;
    } else {
        int prev = unq[i - 1];
        for (int t = prev + 1; t <= cur; t++) g_segstart[t] = i;
    }
    if (i == n - 1) {
        for (int t = cur + 1; t <= s_count; t++) g_segstart[t] = n;
    }
}

// ---------------- K2: input first/second moments ----------------
__global__ void k_moments(const float* __restrict__ inp, int n) {
    float a1[CIN];
    float a2[55];
#pragma unroll
    for (int k = 0; k < CIN; k++) a1[k] = 0.0f;
#pragma unroll
    for (int k = 0; k < 55; k++) a2[k] = 0.0f;

    int stride = gridDim.x * blockDim.x;
    for (int i = blockIdx.x * blockDim.x + threadIdx.x; i < n; i += stride) {
        const float* row = inp + (size_t)i * CIN;
        float v[CIN];
#pragma unroll
        for (int k = 0; k < CIN; k++) v[k] = __ldg(row + k);
        int t = 0;
#pragma unroll
        for (int j = 0; j < CIN; j++) {
            a1[j] += v[j];
#pragma unroll
            for (int k = j; k < CIN; k++) { a2[t] += v[j] * v[k]; t++; }
        }
    }

    int lane = threadIdx.x & 31;
#pragma unroll
    for (int j = 0; j < CIN; j++) {
        float r = warp_sum(a1[j]);
        if (lane == 0) atomicAdd(&g_m1[j], r);
    }
#pragma unroll
    for (int t = 0; t < 55; t++) {
        float r = warp_sum(a2[t]);
        if (lane == 0) atomicAdd(&g_m2[t], r);
    }
}

// ---------------- K3: fold BN into linear + stage packed params ----------------
__global__ void k_fold(const float* __restrict__ W, const float* __restrict__ gamma,
                       const float* __restrict__ beta, const float* __restrict__ dw1,
                       int n) {
    int c = threadIdx.x;
    if (c < C) {
        float invn = 1.0f / (float)n;
        float wr[CIN];
#pragma unroll
        for (int k = 0; k < CIN; k++) wr[k] = W[c * CIN + k];

        float mu = 0.0f;
#pragma unroll
        for (int k = 0; k < CIN; k++) mu += wr[k] * g_m1[k];
        mu *= invn;

        float ex2 = 0.0f;
        int t = 0;
#pragma unroll
        for (int j = 0; j < CIN; j++) {
#pragma unroll
            for (int k = j; k < CIN; k++) {
                float f = wr[j] * wr[k] * g_m2[t];
                ex2 += (k == j) ? f : 2.0f * f;
                t++;
            }
        }
        ex2 *= invn;
        float var = ex2 - mu * mu;
        float alpha = gamma[c] * rsqrtf(var + EPS);
        g_bias[c] = beta[c] - mu * alpha;
#pragma unroll
        for (int k = 0; k < CIN; k++) g_Wf[c * CIN + k] = alpha * wr[k];
    }
    __syncthreads();
    if (c < 32) {
#pragma unroll
        for (int k = 0; k < CIN; k++)
            g_stage.Wfp[c * CIN + k] = pack2(g_Wf[(2 * c) * CIN + k],
                                             g_Wf[(2 * c + 1) * CIN + k]);
        g_stage.biasp[c] = pack2(g_bias[2 * c], g_bias[2 * c + 1]);
        g_stage.dwp[c]   = pack2(dw1[2 * c], dw1[2 * c + 1]);
    }
}

// ---------------- K4: g = sum over points of relu(x), channel-per-thread ----------------
#define GP_TILE 256
__global__ __launch_bounds__(256) void k_gpass(const float* __restrict__ inp, int n) {
    __shared__ __align__(16) float s_v[GP_TILE * 12];
    __shared__ float s_acc[C];

    int t = threadIdx.x;
    int c = t & 63, g = t >> 6;

    float w[CIN];
#pragma unroll
    for (int k = 0; k < CIN; k++) w[k] = g_Wf[c * CIN + k];
    float b = g_bias[c];
    if (t < C) s_acc[t] = 0.0f;

    float acc = 0.0f;
    for (int base = blockIdx.x * GP_TILE; base < n; base += gridDim.x * GP_TILE) {
        int cnt = n - base; if (cnt > GP_TILE) cnt = GP_TILE;
        __syncthreads();
        for (int i = t; i < cnt * CIN; i += 256) {
            int r = i / CIN, k = i - r * CIN;
            s_v[r * 12 + k] = inp[(size_t)base * CIN + i];
        }
        __syncthreads();
        int p0 = g * 64, p1 = p0 + 64; if (p1 > cnt) p1 = cnt;
        for (int p = p0; p < p1; p++) {
            const float* vr = s_v + p * 12;
            float4 va = *reinterpret_cast<const float4*>(vr);
            float4 vb = *reinterpret_cast<const float4*>(vr + 4);
            float2 vc = *reinterpret_cast<const float2*>(vr + 8);
            float x = b;
            x += w[0] * va.x; x += w[1] * va.y; x += w[2] * va.z; x += w[3] * va.w;
            x += w[4] * vb.x; x += w[5] * vb.y; x += w[6] * vb.z; x += w[7] * vb.w;
            x += w[8] * vc.x; x += w[9] * vc.y;
            acc += fmaxf(x, 0.0f);
        }
    }
    atomicAdd(&s_acc[c], acc);
    __syncthreads();
    if (t < C) atomicAdd(&g_gsum[t], s_acc[t]);
}

// ---------------- K5: global branch -> stage xg ----------------
__global__ void k_xg(const float* __restrict__ dw2, const float* __restrict__ pw2, int n) {
    __shared__ float t[C];
    int c = threadIdx.x;
    if (c < C) t[c] = fmaxf(dw2[c] * (g_gsum[c] / (float)n), 0.0f);
    __syncthreads();
    if (c >= C) return;
    float acc = 0.0f;
#pragma unroll
    for (int k = 0; k < C; k++) acc += pw2[c * C + k] * t[k];
    g_stage.xg[c] = acc;
}

// ---------------- K6: fused pipeline, GEMM-tiled phase B ----------------
// dynamic shared layout (bytes):
//   xT   [64][130] f32  @ 0      (33280)  x then xi, transposed [ch][pt]
//   swT  [64][66]  u64  @ 33280  (33792)  sw transposed [ch][pt-pair]
//   pwT  [64][68]  f32  @ 67072  (17408)  pw1 transposed [k][c]
//   Wfp  [32*10]   u64  @ 84480  (2560)
//   bp   [32]      u64  @ 87040  (256)
//   dwp  [32]      u64  @ 87296  (256)
//   xg   [64]      f32  @ 87552  (256)
//   s_u  [128]     int  @ 87808  (512)
#define OFF_SWT 33280
#define OFF_PWT 67072
#define OFF_WFP 84480
#define OFF_BP  87040
#define OFF_DWP 87296
#define OFF_XG  87552
#define OFF_U   87808
#define PIPE_SMEM 88320
#define XT_S  130
#define SWT_S 66
#define PWT_S 68

__global__ __launch_bounds__(128) void k_pipe(const float* __restrict__ inp,
                                              const float* __restrict__ pw1,
                                              const int* __restrict__ unq,
                                              int n) {
    extern __shared__ __align__(16) char dsm[];
    float* xT   = reinterpret_cast<float*>(dsm);
    u64*   swT  = reinterpret_cast<u64*>(dsm + OFF_SWT);
    float* swTf = reinterpret_cast<float*>(dsm + OFF_SWT);
    float* pwT  = reinterpret_cast<float*>(dsm + OFF_PWT);
    const ulonglong2* Wfp2 = reinterpret_cast<const ulonglong2*>(dsm + OFF_WFP);
    u64*   wfpw = reinterpret_cast<u64*>(dsm + OFF_WFP);
    u64*   bp   = reinterpret_cast<u64*>(dsm + OFF_BP);
    u64*   dwp  = reinterpret_cast<u64*>(dsm + OFF_DWP);
    float* s_xg = reinterpret_cast<float*>(dsm + OFF_XG);
    int*   s_u  = reinterpret_cast<int*>(dsm + OFF_U);

    int li = threadIdx.x;
    int base = blockIdx.x * 128;
    int cnt = n - base; if (cnt > 128) cnt = 128;

    // staging: pw1 transpose [c][k] -> pwT[k][c]
    for (int t = li; t < C * C; t += 128) {
        int c = t >> 6, k = t & 63;
        pwT[k * PWT_S + c] = __ldg(pw1 + t);
    }
    for (int t = li; t < 32 * CIN; t += 128) wfpw[t] = g_stage.Wfp[t];
    if (li < 32) { bp[li] = g_stage.biasp[li]; dwp[li] = g_stage.dwp[li]; }
    if (li < C) s_xg[li] = g_stage.xg[li];
    if (li < cnt) s_u[li] = __ldg(unq + base + li);
    __syncthreads();

    // ---- phase A: per-point folded linear + relu + swish, write transposed ----
    if (li < cnt) {
        const float* row = inp + (size_t)(base + li) * CIN;
        u64 vd[CIN];
#pragma unroll
        for (int k = 0; k < CIN; k++) {
            float f = __ldg(row + k);
            vd[k] = pack2(f, f);
        }
#pragma unroll
        for (int cp = 0; cp < 32; cp++) {
            ulonglong2 wA = Wfp2[cp * 5 + 0];
            ulonglong2 wB = Wfp2[cp * 5 + 1];
            ulonglong2 wC = Wfp2[cp * 5 + 2];
            ulonglong2 wD = Wfp2[cp * 5 + 3];
            ulonglong2 wE = Wfp2[cp * 5 + 4];
            u64 a = bp[cp];
            a = fma2(wA.x, vd[0], a); a = fma2(wA.y, vd[1], a);
            a = fma2(wB.x, vd[2], a); a = fma2(wB.y, vd[3], a);
            a = fma2(wC.x, vd[4], a); a = fma2(wC.y, vd[5], a);
            a = fma2(wD.x, vd[6], a); a = fma2(wD.y, vd[7], a);
            a = fma2(wE.x, vd[8], a); a = fma2(wE.y, vd[9], a);
            float lo, hi; unpack2(a, lo, hi);
            lo = fmaxf(lo, 0.0f); hi = fmaxf(hi, 0.0f);
            xT[(2 * cp) * XT_S + li]     = lo;
            xT[(2 * cp + 1) * XT_S + li] = hi;
            u64 sp = mul2(pack2(lo, hi), dwp[cp]);
            float sa, sb; unpack2(sp, sa, sb);
            swTf[(2 * cp) * (2 * SWT_S) + li]     = sa * sigmoidf_fast(sa);
            swTf[(2 * cp + 1) * (2 * SWT_S) + li] = sb * sigmoidf_fast(sb);
        }
    } else {
#pragma unroll
        for (int c = 0; c < C; c++) {
            xT[c * XT_S + li] = 0.0f;
            swTf[c * (2 * SWT_S) + li] = 0.0f;
        }
    }
    __syncthreads();

    // ---- phase B: block GEMM xl[c][pp] = sum_k pwT[k][c] * swT[k][pp] ----
    {
        int c0 = (li & 7) * 8;
        int pp0 = (li >> 3) * 4;
        u64 acc[8][4];
#pragma unroll
        for (int i = 0; i < 8; i++)
#pragma unroll
            for (int j = 0; j < 4; j++) acc[i][j] = 0ull;

#pragma unroll 8
        for (int k = 0; k < C; k++) {
            const ulonglong2* swr = reinterpret_cast<const ulonglong2*>(swT + k * SWT_S + pp0);
            ulonglong2 s01 = swr[0];
            ulonglong2 s23 = swr[1];
            const float4* wr = reinterpret_cast<const float4*>(pwT + k * PWT_S + c0);
            float4 wa = wr[0];
            float4 wb = wr[1];
            u64 wd[8];
            wd[0] = pack2(wa.x, wa.x); wd[1] = pack2(wa.y, wa.y);
            wd[2] = pack2(wa.z, wa.z); wd[3] = pack2(wa.w, wa.w);
            wd[4] = pack2(wb.x, wb.x); wd[5] = pack2(wb.y, wb.y);
            wd[6] = pack2(wb.z, wb.z); wd[7] = pack2(wb.w, wb.w);
#pragma unroll
            for (int i = 0; i < 8; i++) {
                acc[i][0] = fma2(wd[i], s01.x, acc[i][0]);
                acc[i][1] = fma2(wd[i], s01.y, acc[i][1]);
                acc[i][2] = fma2(wd[i], s23.x, acc[i][2]);
                acc[i][3] = fma2(wd[i], s23.y, acc[i][3]);
            }
        }

        // epilogue: wei = sigmoid(xl + xg); xi = x*(1+wei) in place (transposed)
#pragma unroll
        for (int i = 0; i < 8; i++) {
            int c = c0 + i;
            float xgc = s_xg[c];
#pragma unroll
            for (int j = 0; j < 4; j++) {
                float lo, hi; unpack2(acc[i][j], lo, hi);
                int p0 = 2 * (pp0 + j);
                u64* xp = reinterpret_cast<u64*>(xT + c * XT_S + p0);
                float x0, x1; unpack2(*xp, x0, x1);
                float w0 = sigmoidf_fast(lo + xgc);
                float w1 = sigmoidf_fast(hi + xgc);
                *xp = pack2(x0 * (1.0f + w0), x1 * (1.0f + w1));
            }
        }
    }
    __syncthreads();

    // ---- phase C: per-pillar partial (max,sum) per 64-pt subtile -> 2-slot scratch ----
    {
        int h = li >> 6, c = li & 63;
        int p = h * 64, pend = p + 64; if (pend > cnt) pend = cnt;
        if (p < pend) {
            int mytile = (base >> 6) + h;
            int cur = s_u[p];
            float v = xT[c * XT_S + p];
            float mx = v, sm = v;
            for (p++; p < pend; p++) {
                int u = s_u[p];
                float w = xT[c * XT_S + p];
                if (u != cur) {
                    size_t slot = ((g_segstart[cur] >> 6) == mytile) ? 0 : 1;
                    size_t idx = slot * ((size_t)SMAX * C) + (size_t)cur * C + c;
                    g_pmax[idx] = mx;
                    g_psum[idx] = sm;
                    cur = u; mx = w; sm = w;
                } else {
                    mx = fmaxf(mx, w); sm += w;
                }
            }
            size_t slot = ((g_segstart[cur] >> 6) == mytile) ? 0 : 1;
            size_t idx = slot * ((size_t)SMAX * C) + (size_t)cur * C + c;
            g_pmax[idx] = mx;
            g_psum[idx] = sm;
        }
    }
}

// ---------------- K7: combine per-pillar partials -> out ----------------
__global__ __launch_bounds__(256) void k_combine(float* __restrict__ out, int s_count) {
    int s = blockIdx.x * 8 + (threadIdx.x >> 5);
    int lane = threadIdx.x & 31;
    if (s >= s_count) return;
    int p0 = g_segstart[s], p1 = g_segstart[s + 1];
    size_t i0 = (size_t)s * C + 2 * lane;
    if (p1 <= p0) {
        out[i0] = 0.0f; out[i0 + 1] = 0.0f;
        return;
    }
    float2 m = *reinterpret_cast<const float2*>(g_pmax + i0);
    float2 q = *reinterpret_cast<const float2*>(g_psum + i0);
    if (((p1 - 1) >> 6) > (p0 >> 6)) {
        size_t i1 = (size_t)SMAX * C + i0;
        float2 m1 = *reinterpret_cast<const float2*>(g_pmax + i1);
        float2 q1 = *reinterpret_cast<const float2*>(g_psum + i1);
        m.x = fmaxf(m.x, m1.x); m.y = fmaxf(m.y, m1.y);
        q.x += q1.x; q.y += q1.y;
    }
    *reinterpret_cast<float2*>(out + i0) = make_float2(m.x + q.x, m.y + q.y);
}

// ---------------- launch ----------------
extern "C" void kernel_launch(void* const* d_in, const int* in_sizes, int n_in,
                              void* d_out, int out_size) {
    const float* inp   = (const float*)d_in[0];
    const int*   unq   = (const int*)d_in[1];
    const float* W     = (const float*)d_in[2];
    const float* gamma = (const float*)d_in[3];
    const float* beta  = (const float*)d_in[4];
    const float* dw1   = (const float*)d_in[5];
    const float* pw1   = (const float*)d_in[6];
    const float* dw2   = (const float*)d_in[7];
    const float* pw2   = (const float*)d_in[8];
    float* out = (float*)d_out;

    int n = in_sizes[0] / CIN;     // 1,000,000
    int s = out_size / C;          // 30,000

    static bool attr_done = false;
    if (!attr_done) {
        cudaFuncSetAttribute(k_pipe, cudaFuncAttributeMaxDynamicSharedMemorySize,
                             PIPE_SMEM);
        attr_done = true;
    }

    k_bounds<<<(n + 255) / 256, 256>>>(unq, n, s);                 // launch 1
    k_moments<<<592, 256>>>(inp, n);                               // launch 2
    k_fold<<<1, 64>>>(W, gamma, beta, dw1, n);                     // launch 3
    k_gpass<<<592, 256>>>(inp, n);                                 // launch 4
    k_xg<<<1, 64>>>(dw2, pw2, n);                                  // launch 5
    k_pipe<<<(n + 127) / 128, 128, PIPE_SMEM>>>(inp, pw1, unq, n); // launch 6
    k_combine<<<(s + 7) / 8, 256>>>(out, s);                       // launch 7
}

// round 11
// speedup vs baseline: 1.1362x; 1.1362x over previous
#include <cuda_runtime.h>
#include <cstdint>

#define CIN  10
#define C    64
#define SMAX 30001
#define EPS  1e-3f
#define FULLMASK 0xffffffffu

typedef unsigned long long u64;

// ---------------- parameter staging (read by k_pipe into shared) ----------------
struct Params {
    u64   Wfp[32 * CIN];   // BN-folded linear weights, channel-pair packed
    u64   biasp[32];
    u64   dwp[32];
    float xg[C];
};
__device__ Params g_stage;

// ---------------- device scratch ----------------
__device__ float g_m1[CIN];
__device__ float g_m2[55];
__device__ float g_Wf[C * CIN];
__device__ float g_bias[C];
__device__ float g_gsum[C];
__device__ int   g_segstart[SMAX];
// per-pillar partials, 2 slots (pillar-start subtile / spill subtile)
__device__ float g_pmax[(size_t)2 * SMAX * C];
__device__ float g_psum[(size_t)2 * SMAX * C];

// ---------------- packed f32x2 / bf16 helpers ----------------
__device__ __forceinline__ u64 pack2(float lo, float hi) {
    u64 r; asm("mov.b64 %0, {%1, %2};" : "=l"(r) : "f"(lo), "f"(hi)); return r;
}
__device__ __forceinline__ void unpack2(u64 v, float& lo, float& hi) {
    asm("mov.b64 {%0, %1}, %2;" : "=f"(lo), "=f"(hi) : "l"(v));
}
__device__ __forceinline__ u64 fma2(u64 a, u64 b, u64 c) {
    u64 d; asm("fma.rn.f32x2 %0, %1, %2, %3;" : "=l"(d) : "l"(a), "l"(b), "l"(c)); return d;
}
__device__ __forceinline__ u64 mul2(u64 a, u64 b) {
    u64 d; asm("mul.rn.f32x2 %0, %1, %2;" : "=l"(d) : "l"(a), "l"(b)); return d;
}
// duplicate one f32 (given as raw bits) into both halves of an f32x2 register pair
__device__ __forceinline__ u64 dup2u(unsigned int v) {
    u64 r; asm("mov.b64 %0, {%1, %1};" : "=l"(r) : "r"(v)); return r;
}
// pack two f32 -> bf16x2 (hi goes to upper half)
__device__ __forceinline__ unsigned int cvt2bf(float hi, float lo) {
    unsigned int r;
    asm("cvt.rn.satfinite.bf16x2.f32 %0, %1, %2;" : "=r"(r) : "f"(hi), "f"(lo));
    return r;
}

__device__ __forceinline__ float sigmoidf_fast(float z) {
    return __fdividef(1.0f, 1.0f + __expf(-z));
}
__device__ __forceinline__ float warp_sum(float v) {
#pragma unroll
    for (int o = 16; o > 0; o >>= 1) v += __shfl_down_sync(FULLMASK, v, o);
    return v;
}

// ---------------- K1: zero accumulators + segment boundaries ----------------
__global__ void k_bounds(const int* __restrict__ unq, int n, int s_count) {
    if (blockIdx.x == 0) {
        int t = threadIdx.x;
        if (t < CIN) g_m1[t] = 0.0f;
        if (t < 55)  g_m2[t] = 0.0f;
        if (t < C)   g_gsum[t] = 0.0f;
    }
    int i = blockIdx.x * blockDim.x + threadIdx.x;
    if (i >= n) return;
    int cur = unq[i];
    if (i == 0) {
        for (int t = 0; t <= cur; t++) g_segstart[t] = 0;
    } else {
        int prev = unq[i - 1];
        for (int t = prev + 1; t <= cur; t++) g_segstart[t] = i;
    }
    if (i == n - 1) {
        for (int t = cur + 1; t <= s_count; t++) g_segstart[t] = n;
    }
}

// ---------------- K2: input first/second moments ----------------
__global__ void k_moments(const float* __restrict__ inp, int n) {
    float a1[CIN];
    float a2[55];
#pragma unroll
    for (int k = 0; k < CIN; k++) a1[k] = 0.0f;
#pragma unroll
    for (int k = 0; k < 55; k++) a2[k] = 0.0f;

    int stride = gridDim.x * blockDim.x;
    for (int i = blockIdx.x * blockDim.x + threadIdx.x; i < n; i += stride) {
        const float* row = inp + (size_t)i * CIN;
        float v[CIN];
#pragma unroll
        for (int k = 0; k < CIN; k++) v[k] = __ldg(row + k);
        int t = 0;
#pragma unroll
        for (int j = 0; j < CIN; j++) {
            a1[j] += v[j];
#pragma unroll
            for (int k = j; k < CIN; k++) { a2[t] += v[j] * v[k]; t++; }
        }
    }

    int lane = threadIdx.x & 31;
#pragma unroll
    for (int j = 0; j < CIN; j++) {
        float r = warp_sum(a1[j]);
        if (lane == 0) atomicAdd(&g_m1[j], r);
    }
#pragma unroll
    for (int t = 0; t < 55; t++) {
        float r = warp_sum(a2[t]);
        if (lane == 0) atomicAdd(&g_m2[t], r);
    }
}

// ---------------- K3: fold BN into linear + stage packed params ----------------
__global__ void k_fold(const float* __restrict__ W, const float* __restrict__ gamma,
                       const float* __restrict__ beta, const float* __restrict__ dw1,
                       int n) {
    int c = threadIdx.x;
    if (c < C) {
        float invn = 1.0f / (float)n;
        float wr[CIN];
#pragma unroll
        for (int k = 0; k < CIN; k++) wr[k] = W[c * CIN + k];

        float mu = 0.0f;
#pragma unroll
        for (int k = 0; k < CIN; k++) mu += wr[k] * g_m1[k];
        mu *= invn;

        float ex2 = 0.0f;
        int t = 0;
#pragma unroll
        for (int j = 0; j < CIN; j++) {
#pragma unroll
            for (int k = j; k < CIN; k++) {
                float f = wr[j] * wr[k] * g_m2[t];
                ex2 += (k == j) ? f : 2.0f * f;
                t++;
            }
        }
        ex2 *= invn;
        float var = ex2 - mu * mu;
        float alpha = gamma[c] * rsqrtf(var + EPS);
        g_bias[c] = beta[c] - mu * alpha;
#pragma unroll
        for (int k = 0; k < CIN; k++) g_Wf[c * CIN + k] = alpha * wr[k];
    }
    __syncthreads();
    if (c < 32) {
#pragma unroll
        for (int k = 0; k < CIN; k++)
            g_stage.Wfp[c * CIN + k] = pack2(g_Wf[(2 * c) * CIN + k],
                                             g_Wf[(2 * c + 1) * CIN + k]);
        g_stage.biasp[c] = pack2(g_bias[2 * c], g_bias[2 * c + 1]);
        g_stage.dwp[c]   = pack2(dw1[2 * c], dw1[2 * c + 1]);
    }
}

// ---------------- K4: g = sum over points of relu(x), channel-per-thread ----------------
#define GP_TILE 256
__global__ __launch_bounds__(256) void k_gpass(const float* __restrict__ inp, int n) {
    __shared__ __align__(16) float s_v[GP_TILE * 12];
    __shared__ float s_acc[C];

    int t = threadIdx.x;
    int c = t & 63, g = t >> 6;

    float w[CIN];
#pragma unroll
    for (int k = 0; k < CIN; k++) w[k] = g_Wf[c * CIN + k];
    float b = g_bias[c];
    if (t < C) s_acc[t] = 0.0f;

    float acc = 0.0f;
    for (int base = blockIdx.x * GP_TILE; base < n; base += gridDim.x * GP_TILE) {
        int cnt = n - base; if (cnt > GP_TILE) cnt = GP_TILE;
        __syncthreads();
        for (int i = t; i < cnt * CIN; i += 256) {
            int r = i / CIN, k = i - r * CIN;
            s_v[r * 12 + k] = inp[(size_t)base * CIN + i];
        }
        __syncthreads();
        int p0 = g * 64, p1 = p0 + 64; if (p1 > cnt) p1 = cnt;
        for (int p = p0; p < p1; p++) {
            const float* vr = s_v + p * 12;
            float4 va = *reinterpret_cast<const float4*>(vr);
            float4 vb = *reinterpret_cast<const float4*>(vr + 4);
            float2 vc = *reinterpret_cast<const float2*>(vr + 8);
            float x = b;
            x += w[0] * va.x; x += w[1] * va.y; x += w[2] * va.z; x += w[3] * va.w;
            x += w[4] * vb.x; x += w[5] * vb.y; x += w[6] * vb.z; x += w[7] * vb.w;
            x += w[8] * vc.x; x += w[9] * vc.y;
            acc += fmaxf(x, 0.0f);
        }
    }
    atomicAdd(&s_acc[c], acc);
    __syncthreads();
    if (t < C) atomicAdd(&g_gsum[t], s_acc[t]);
}

// ---------------- K5: global branch -> stage xg ----------------
__global__ void k_xg(const float* __restrict__ dw2, const float* __restrict__ pw2, int n) {
    __shared__ float t[C];
    int c = threadIdx.x;
    if (c < C) t[c] = fmaxf(dw2[c] * (g_gsum[c] / (float)n), 0.0f);
    __syncthreads();
    if (c >= C) return;
    float acc = 0.0f;
#pragma unroll
    for (int k = 0; k < C; k++) acc += pw2[c * C + k] * t[k];
    g_stage.xg[c] = acc;
}

// ---------------- K6: fused pipeline, bf16-sw GEMM phase B ----------------
// dynamic shared layout (bytes):
//   xT   [64][130] f32      @ 0      (33280)  x then xi, transposed [ch][pt]
//   swB  [32][132] u32      @ 33280  (16896)  sw bf16x2, row = k-pair, col = point
//   pwT  [64][68]  f32      @ 50176  (17408)  pw1 transposed [k][c]
//   Wfp  [32*10]   u64      @ 67584  (2560)
//   bp   [32]      u64      @ 70144  (256)
//   dwp  [32]      u64      @ 70400  (256)
//   xg   [64]      f32      @ 70656  (256)
//   s_u  [128]     int      @ 70912  (512)
#define XT_S    130
#define SWB_S   132
#define PWT_S   68
#define OFF_SWB 33280
#define OFF_PWT 50176
#define OFF_WFP 67584
#define OFF_BP  70144
#define OFF_DWP 70400
#define OFF_XG  70656
#define OFF_U   70912
#define PIPE_SMEM 71424

__global__ __launch_bounds__(128, 3) void k_pipe(const float* __restrict__ inp,
                                                 const float* __restrict__ pw1,
                                                 const int* __restrict__ unq,
                                                 int n) {
    extern __shared__ __align__(16) char dsm[];
    float* xT   = reinterpret_cast<float*>(dsm);
    unsigned int* swB = reinterpret_cast<unsigned int*>(dsm + OFF_SWB);
    float* pwT  = reinterpret_cast<float*>(dsm + OFF_PWT);
    const ulonglong2* Wfp2 = reinterpret_cast<const ulonglong2*>(dsm + OFF_WFP);
    u64*   wfpw = reinterpret_cast<u64*>(dsm + OFF_WFP);
    u64*   bp   = reinterpret_cast<u64*>(dsm + OFF_BP);
    u64*   dwp  = reinterpret_cast<u64*>(dsm + OFF_DWP);
    float* s_xg = reinterpret_cast<float*>(dsm + OFF_XG);
    int*   s_u  = reinterpret_cast<int*>(dsm + OFF_U);

    int li = threadIdx.x;
    int base = blockIdx.x * 128;
    int cnt = n - base; if (cnt > 128) cnt = 128;

    // staging: pw1 transpose [c][k] -> pwT[k][c]
    for (int t = li; t < C * C; t += 128) {
        int c = t >> 6, k = t & 63;
        pwT[k * PWT_S + c] = __ldg(pw1 + t);
    }
    for (int t = li; t < 32 * CIN; t += 128) wfpw[t] = g_stage.Wfp[t];
    if (li < 32) { bp[li] = g_stage.biasp[li]; dwp[li] = g_stage.dwp[li]; }
    if (li < C) s_xg[li] = g_stage.xg[li];
    if (li < cnt) s_u[li] = __ldg(unq + base + li);
    __syncthreads();

    // ---- phase A: per-point folded linear + relu + swish (x -> xT, sw -> swB bf16) ----
    if (li < cnt) {
        const float* row = inp + (size_t)(base + li) * CIN;
        u64 vd[CIN];
#pragma unroll
        for (int k = 0; k < CIN; k++) {
            float f = __ldg(row + k);
            vd[k] = pack2(f, f);
        }
#pragma unroll
        for (int cp = 0; cp < 32; cp++) {
            ulonglong2 wA = Wfp2[cp * 5 + 0];
            ulonglong2 wB = Wfp2[cp * 5 + 1];
            ulonglong2 wC = Wfp2[cp * 5 + 2];
            ulonglong2 wD = Wfp2[cp * 5 + 3];
            ulonglong2 wE = Wfp2[cp * 5 + 4];
            u64 a = bp[cp];
            a = fma2(wA.x, vd[0], a); a = fma2(wA.y, vd[1], a);
            a = fma2(wB.x, vd[2], a); a = fma2(wB.y, vd[3], a);
            a = fma2(wC.x, vd[4], a); a = fma2(wC.y, vd[5], a);
            a = fma2(wD.x, vd[6], a); a = fma2(wD.y, vd[7], a);
            a = fma2(wE.x, vd[8], a); a = fma2(wE.y, vd[9], a);
            float lo, hi; unpack2(a, lo, hi);
            lo = fmaxf(lo, 0.0f); hi = fmaxf(hi, 0.0f);
            xT[(2 * cp) * XT_S + li]     = lo;
            xT[(2 * cp + 1) * XT_S + li] = hi;
            u64 sp = mul2(pack2(lo, hi), dwp[cp]);
            float sa, sb; unpack2(sp, sa, sb);
            float swa = sa * sigmoidf_fast(sa);
            float swb = sb * sigmoidf_fast(sb);
            swB[cp * SWB_S + li] = cvt2bf(swb, swa);   // lo16 = k even, hi16 = k odd
        }
    } else {
#pragma unroll
        for (int c = 0; c < C; c++) xT[c * XT_S + li] = 0.0f;
#pragma unroll
        for (int cp = 0; cp < 32; cp++) swB[cp * SWB_S + li] = 0u;
    }
    __syncthreads();

    // ---- phase B: block GEMM xl[c][p] = sum_k pwT[k][c] * sw[k][p] ----
    {
        int c0 = (li & 7) * 8;      // 8 channels = 4 channel-pairs
        int p0 = (li >> 3) * 8;     // 8 points
        u64 acc[4][8];
#pragma unroll
        for (int i = 0; i < 4; i++)
#pragma unroll
            for (int p = 0; p < 8; p++) acc[i][p] = 0ull;

#pragma unroll 4
        for (int kp = 0; kp < 32; kp++) {
            const uint4* svp = reinterpret_cast<const uint4*>(swB + kp * SWB_S + p0);
            uint4 sA = svp[0], sB = svp[1];
            unsigned int sv[8] = {sA.x, sA.y, sA.z, sA.w, sB.x, sB.y, sB.z, sB.w};
            const u64* w0 = reinterpret_cast<const u64*>(pwT + (2 * kp) * PWT_S + c0);
            const u64* w1 = reinterpret_cast<const u64*>(pwT + (2 * kp + 1) * PWT_S + c0);
            u64 wa0 = w0[0], wa1 = w0[1], wa2 = w0[2], wa3 = w0[3];
            u64 wb0 = w1[0], wb1 = w1[1], wb2 = w1[2], wb3 = w1[3];
#pragma unroll
            for (int p = 0; p < 8; p++) {
                u64 se = dup2u(sv[p] << 16);          // k = 2kp
                u64 so = dup2u(sv[p] & 0xffff0000u);  // k = 2kp+1
                acc[0][p] = fma2(wa0, se, acc[0][p]);
                acc[1][p] = fma2(wa1, se, acc[1][p]);
                acc[2][p] = fma2(wa2, se, acc[2][p]);
                acc[3][p] = fma2(wa3, se, acc[3][p]);
                acc[0][p] = fma2(wb0, so, acc[0][p]);
                acc[1][p] = fma2(wb1, so, acc[1][p]);
                acc[2][p] = fma2(wb2, so, acc[2][p]);
                acc[3][p] = fma2(wb3, so, acc[3][p]);
            }
        }

        // epilogue: wei = sigmoid(xl + xg); xi = x*(1+wei) in place (row-wise u64)
#pragma unroll
        for (int i = 0; i < 4; i++) {
            int ca = c0 + 2 * i, cb = ca + 1;
            float xga = s_xg[ca], xgb = s_xg[cb];
            float wa[8], wb[8];
#pragma unroll
            for (int p = 0; p < 8; p++) {
                float la, lb; unpack2(acc[i][p], la, lb);
                wa[p] = 1.0f + sigmoidf_fast(la + xga);
                wb[p] = 1.0f + sigmoidf_fast(lb + xgb);
            }
            u64* ra = reinterpret_cast<u64*>(xT + ca * XT_S + p0);
            u64* rb = reinterpret_cast<u64*>(xT + cb * XT_S + p0);
#pragma unroll
            for (int j = 0; j < 4; j++) {
                ra[j] = mul2(ra[j], pack2(wa[2 * j], wa[2 * j + 1]));
                rb[j] = mul2(rb[j], pack2(wb[2 * j], wb[2 * j + 1]));
            }
        }
    }
    __syncthreads();

    // ---- phase C: per-pillar partial (max,sum) per 64-pt subtile -> 2-slot scratch ----
    {
        int h = li >> 6, c = li & 63;
        int p = h * 64, pend = p + 64; if (pend > cnt) pend = cnt;
        if (p < pend) {
            int mytile = (base >> 6) + h;
            int cur = s_u[p];
            float v = xT[c * XT_S + p];
            float mx = v, sm = v;
            for (p++; p < pend; p++) {
                int u = s_u[p];
                float w = xT[c * XT_S + p];
                if (u != cur) {
                    size_t slot = ((g_segstart[cur] >> 6) == mytile) ? 0 : 1;
                    size_t idx = slot * ((size_t)SMAX * C) + (size_t)cur * C + c;
                    g_pmax[idx] = mx;
                    g_psum[idx] = sm;
                    cur = u; mx = w; sm = w;
                } else {
                    mx = fmaxf(mx, w); sm += w;
                }
            }
            size_t slot = ((g_segstart[cur] >> 6) == mytile) ? 0 : 1;
            size_t idx = slot * ((size_t)SMAX * C) + (size_t)cur * C + c;
            g_pmax[idx] = mx;
            g_psum[idx] = sm;
        }
    }
}

// ---------------- K7: combine per-pillar partials -> out ----------------
__global__ __launch_bounds__(256) void k_combine(float* __restrict__ out, int s_count) {
    int s = blockIdx.x * 8 + (threadIdx.x >> 5);
    int lane = threadIdx.x & 31;
    if (s >= s_count) return;
    int p0 = g_segstart[s], p1 = g_segstart[s + 1];
    size_t i0 = (size_t)s * C + 2 * lane;
    if (p1 <= p0) {
        out[i0] = 0.0f; out[i0 + 1] = 0.0f;
        return;
    }
    float2 m = *reinterpret_cast<const float2*>(g_pmax + i0);
    float2 q = *reinterpret_cast<const float2*>(g_psum + i0);
    if (((p1 - 1) >> 6) > (p0 >> 6)) {
        size_t i1 = (size_t)SMAX * C + i0;
        float2 m1 = *reinterpret_cast<const float2*>(g_pmax + i1);
        float2 q1 = *reinterpret_cast<const float2*>(g_psum + i1);
        m.x = fmaxf(m.x, m1.x); m.y = fmaxf(m.y, m1.y);
        q.x += q1.x; q.y += q1.y;
    }
    *reinterpret_cast<float2*>(out + i0) = make_float2(m.x + q.x, m.y + q.y);
}

// ---------------- launch ----------------
extern "C" void kernel_launch(void* const* d_in, const int* in_sizes, int n_in,
                              void* d_out, int out_size) {
    const float* inp   = (const float*)d_in[0];
    const int*   unq   = (const int*)d_in[1];
    const float* W     = (const float*)d_in[2];
    const float* gamma = (const float*)d_in[3];
    const float* beta  = (const float*)d_in[4];
    const float* dw1   = (const float*)d_in[5];
    const float* pw1   = (const float*)d_in[6];
    const float* dw2   = (const float*)d_in[7];
    const float* pw2   = (const float*)d_in[8];
    float* out = (float*)d_out;

    int n = in_sizes[0] / CIN;     // 1,000,000
    int s = out_size / C;          // 30,000

    static bool attr_done = false;
    if (!attr_done) {
        cudaFuncSetAttribute(k_pipe, cudaFuncAttributeMaxDynamicSharedMemorySize,
                             PIPE_SMEM);
        attr_done = true;
    }

    k_bounds<<<(n + 255) / 256, 256>>>(unq, n, s);                 // launch 1
    k_moments<<<592, 256>>>(inp, n);                               // launch 2
    k_fold<<<1, 64>>>(W, gamma, beta, dw1, n);                     // launch 3
    k_gpass<<<592, 256>>>(inp, n);                                 // launch 4
    k_xg<<<1, 64>>>(dw2, pw2, n);                                  // launch 5
    k_pipe<<<(n + 127) / 128, 128, PIPE_SMEM>>>(inp, pw1, unq, n); // launch 6
    k_combine<<<(s + 7) / 8, 256>>>(out, s);                       // launch 7
}